// round 11
// baseline (speedup 1.0000x reference)
#include <cuda_runtime.h>
#include <cstdint>

// Problem constants (fixed by the dataset)
#define NN 250000
#define DD 128
#define FF 512
#define BB 5000

// Output layout (tuple order, row-major, concatenated):
#define OFF_M        0
#define OFF_INST     5000
#define OFF_Z        2565000
#define OFF_LOC      3205000
#define OFF_MU       3455000
#define OFF_STD      4095000

// Per-bag packed (encoded loc | (N - index)) argmax scratch.
// Zero at module load; gather_kernel re-zeroes after each consume, so no
// init kernel is needed and graph replays stay deterministic.
__device__ unsigned long long g_seg[BB];

// Order-preserving bijection float -> uint32 (monotonic, injective).
__device__ __forceinline__ unsigned enc_float(float f) {
    unsigned bits = __float_as_uint(f);
    return (bits & 0x80000000u) ? ~bits : (bits | 0x80000000u);
}
__device__ __forceinline__ float dec_float(unsigned e) {
    unsigned bits = (e & 0x80000000u) ? (e ^ 0x80000000u) : ~e;
    return __uint_as_float(bits);
}

#define ROWS_PER_WARP 8

// Warp handles 8 rows: loads front-batched (MLP=8), then 8 pipelined
// butterfly reductions; lanes 0..7 each finalize one row.
__global__ void __launch_bounds__(256) loc_kernel(
        const float* __restrict__ z,
        const int*   __restrict__ bag,
        const float* __restrict__ W,
        const float* __restrict__ b,
        float*       __restrict__ loc_out) {
    const int warp = (blockIdx.x * blockDim.x + threadIdx.x) >> 5;
    const int lane = threadIdx.x & 31;
    const int row0 = warp * ROWS_PER_WARP;
    if (row0 >= NN) return;

    const float4 wv = __ldg(&reinterpret_cast<const float4*>(W)[lane]);

    // Front-batch the 8 row loads (independent -> MLP=8).
    float4 zv[ROWS_PER_WARP];
    const float4* z4 = reinterpret_cast<const float4*>(z) + (size_t)row0 * (DD / 4) + lane;
    #pragma unroll
    for (int r = 0; r < ROWS_PER_WARP; r++) {
        if (row0 + r < NN) zv[r] = z4[(size_t)r * (DD / 4)];
        else               zv[r] = make_float4(0.f, 0.f, 0.f, 0.f);
    }

    float s[ROWS_PER_WARP];
    #pragma unroll
    for (int r = 0; r < ROWS_PER_WARP; r++)
        s[r] = fmaf(zv[r].x, wv.x, fmaf(zv[r].y, wv.y, fmaf(zv[r].z, wv.z, zv[r].w * wv.w)));

    #pragma unroll
    for (int off = 16; off; off >>= 1) {
        #pragma unroll
        for (int r = 0; r < ROWS_PER_WARP; r++)
            s[r] += __shfl_xor_sync(0xFFFFFFFFu, s[r], off);
    }

    if (lane < ROWS_PER_WARP) {
        const int row = row0 + lane;
        if (row < NN) {
            float v = s[0];
            #pragma unroll
            for (int r = 1; r < ROWS_PER_WARP; r++)
                if (lane == r) v = s[r];
            v += __ldg(b);
            loc_out[row] = v;
            unsigned long long packed =
                ((unsigned long long)enc_float(v) << 32) | (unsigned)(NN - row);
            atomicMax(&g_seg[bag[row]], packed);  // no return use -> REDG path
        }
    }
}

// Warp per bag: broadcast g_seg load, then 7 independent float4 loads per
// lane (4 inst + z + mu + sd), all front-issued. No block barrier; lane 0
// resets the scratch slot after __syncwarp so graph replays stay correct.
// Empty bags handled branch-free: idx clamped to 0, rows loaded anyway,
// zero selected at store.
__global__ void __launch_bounds__(256) gather_kernel(
        const float* __restrict__ z,
        const float* __restrict__ inst,
        const float* __restrict__ mu,
        const float* __restrict__ sd,
        float*       __restrict__ out) {
    const int warp  = (blockIdx.x * blockDim.x + threadIdx.x) >> 5;
    const int lane  = threadIdx.x & 31;
    if (warp >= BB) return;
    const int bagid = warp;

    const unsigned long long p = g_seg[bagid];  // same addr across warp -> broadcast
    const bool  empty = (p == 0ULL);
    const int   idx   = empty ? 0 : (NN - (int)(unsigned)(p & 0xFFFFFFFFu));

    // Front-issue all loads (independent -> MLP=7 per lane).
    const float4* s_inst = reinterpret_cast<const float4*>(inst + (size_t)idx * FF);
    float4 iv0 = s_inst[lane +  0];
    float4 iv1 = s_inst[lane + 32];
    float4 iv2 = s_inst[lane + 64];
    float4 iv3 = s_inst[lane + 96];
    float4 zv  = reinterpret_cast<const float4*>(z  + (size_t)idx * DD)[lane];
    float4 mv  = reinterpret_cast<const float4*>(mu + (size_t)idx * DD)[lane];
    float4 sv  = reinterpret_cast<const float4*>(sd + (size_t)idx * DD)[lane];

    const float4 zero4 = make_float4(0.f, 0.f, 0.f, 0.f);
    if (empty) { iv0 = zero4; iv1 = zero4; iv2 = zero4; iv3 = zero4;
                 zv = zero4;  mv = zero4;  sv = zero4; }

    float4* o_inst = reinterpret_cast<float4*>(out + OFF_INST + (size_t)bagid * FF);
    o_inst[lane +  0] = iv0;
    o_inst[lane + 32] = iv1;
    o_inst[lane + 64] = iv2;
    o_inst[lane + 96] = iv3;
    reinterpret_cast<float4*>(out + OFF_Z   + (size_t)bagid * DD)[lane] = zv;
    reinterpret_cast<float4*>(out + OFF_MU  + (size_t)bagid * DD)[lane] = mv;
    reinterpret_cast<float4*>(out + OFF_STD + (size_t)bagid * DD)[lane] = sv;

    if (lane == 0) out[OFF_M + bagid] = empty ? 0.f : dec_float((unsigned)(p >> 32));

    // All lanes consumed p (read at warp entry); reset for next replay.
    __syncwarp();
    if (lane == 0) g_seg[bagid] = 0ULL;
}

extern "C" void kernel_launch(void* const* d_in, const int* in_sizes, int n_in,
                              void* d_out, int out_size) {
    const float* z_ins   = (const float*)d_in[0];
    const int*   bag_idx = (const int*)  d_in[1];
    const float* inst    = (const float*)d_in[2];
    const float* mu      = (const float*)d_in[3];
    const float* sd      = (const float*)d_in[4];
    const float* W       = (const float*)d_in[5];
    const float* b       = (const float*)d_in[6];
    float* out = (float*)d_out;

    // 8 warps/block, 8 rows/warp -> 64 rows/block.
    const int rows_per_block = 8 * ROWS_PER_WARP;
    const int blocks = (NN + rows_per_block - 1) / rows_per_block;
    loc_kernel<<<blocks, 256>>>(z_ins, bag_idx, W, b, out + OFF_LOC);

    // Warp per bag: 5000 warps -> 625 blocks of 256 threads.
    gather_kernel<<<(BB + 7) / 8, 256>>>(z_ins, inst, mu, sd, out);
}

// round 12
// speedup vs baseline: 1.0703x; 1.0703x over previous
#include <cuda_runtime.h>
#include <cstdint>

// Problem constants (fixed by the dataset)
#define NN 250000
#define DD 128
#define FF 512
#define BB 5000

// Output layout (tuple order, row-major, concatenated):
#define OFF_M        0
#define OFF_INST     5000
#define OFF_Z        2565000
#define OFF_LOC      3205000
#define OFF_MU       3455000
#define OFF_STD      4095000

// Per-bag packed (encoded loc | (N - index)) argmax scratch.
// Zero at module load; gather_kernel re-zeroes after each consume, so no
// init kernel is needed and graph replays stay deterministic.
__device__ unsigned long long g_seg[BB];

// Order-preserving bijection float -> uint32 (monotonic, injective).
__device__ __forceinline__ unsigned enc_float(float f) {
    unsigned bits = __float_as_uint(f);
    return (bits & 0x80000000u) ? ~bits : (bits | 0x80000000u);
}
__device__ __forceinline__ float dec_float(unsigned e) {
    unsigned bits = (e & 0x80000000u) ? (e ^ 0x80000000u) : ~e;
    return __uint_as_float(bits);
}

#define ROWS_PER_WARP 8
#define ROWS_PER_BLOCK 64   // 8 warps * 8 rows

// Warp handles 8 rows: loads front-batched, butterfly reductions, then the
// per-bag argmax is aggregated in SHARED memory (bag_idx is sorted, so a
// 64-row block spans few bags) and flushed with ~2-3 global atomics per
// block instead of 64. Wide-span blocks (mostly-empty bag regions) fall
// back to direct global atomics -- deterministic either way.
__global__ void __launch_bounds__(256) loc_kernel(
        const float* __restrict__ z,
        const int*   __restrict__ bag,
        const float* __restrict__ W,
        const float* __restrict__ b,
        float*       __restrict__ loc_out) {
    __shared__ unsigned long long sseg[ROWS_PER_BLOCK + 1];
    __shared__ int s_baglo, s_span;

    const int wid  = threadIdx.x >> 5;
    const int lane = threadIdx.x & 31;
    const int row0_blk = blockIdx.x * ROWS_PER_BLOCK;
    const int row0 = row0_blk + wid * ROWS_PER_WARP;

    // Block bag range (sorted bag_idx -> all rows' bags lie in [lo, hi]).
    if (threadIdx.x == 0) {
        int lo = bag[min(row0_blk, NN - 1)];
        int hi = bag[min(row0_blk + ROWS_PER_BLOCK - 1, NN - 1)];
        s_baglo = lo;
        s_span  = hi - lo;
    }
    if (threadIdx.x <= ROWS_PER_BLOCK) sseg[threadIdx.x] = 0ULL;
    __syncthreads();
    const int baglo = s_baglo;
    const int span  = s_span;
    const bool use_smem = (span <= ROWS_PER_BLOCK);

    if (row0 < NN) {
        const float4 wv = __ldg(&reinterpret_cast<const float4*>(W)[lane]);

        // Front-batch the 8 row loads (independent -> MLP=8).
        float4 zv[ROWS_PER_WARP];
        const float4* z4 = reinterpret_cast<const float4*>(z) + (size_t)row0 * (DD / 4) + lane;
        #pragma unroll
        for (int r = 0; r < ROWS_PER_WARP; r++) {
            if (row0 + r < NN) zv[r] = z4[(size_t)r * (DD / 4)];
            else               zv[r] = make_float4(0.f, 0.f, 0.f, 0.f);
        }

        float s[ROWS_PER_WARP];
        #pragma unroll
        for (int r = 0; r < ROWS_PER_WARP; r++)
            s[r] = fmaf(zv[r].x, wv.x, fmaf(zv[r].y, wv.y, fmaf(zv[r].z, wv.z, zv[r].w * wv.w)));

        #pragma unroll
        for (int off = 16; off; off >>= 1) {
            #pragma unroll
            for (int r = 0; r < ROWS_PER_WARP; r++)
                s[r] += __shfl_xor_sync(0xFFFFFFFFu, s[r], off);
        }

        if (lane < ROWS_PER_WARP) {
            const int row = row0 + lane;
            if (row < NN) {
                float v = s[0];
                #pragma unroll
                for (int r = 1; r < ROWS_PER_WARP; r++)
                    if (lane == r) v = s[r];
                v += __ldg(b);
                loc_out[row] = v;
                const int bg = bag[row];
                unsigned long long packed =
                    ((unsigned long long)enc_float(v) << 32) | (unsigned)(NN - row);
                if (use_smem) atomicMax(&sseg[bg - baglo], packed);
                else          atomicMax(&g_seg[bg], packed);
            }
        }
    }

    __syncthreads();
    // Flush shared aggregates: only the few nonzero slots hit global atomics.
    if (use_smem && threadIdx.x <= span) {
        unsigned long long v = sseg[threadIdx.x];
        if (v != 0ULL) atomicMax(&g_seg[baglo + threadIdx.x], v);
    }
}

// Warp per bag: broadcast g_seg load, then 7 independent float4 loads per
// lane (4 inst + z + mu + sd), all front-issued. No block barrier; lane 0
// resets the scratch slot after __syncwarp so graph replays stay correct.
__global__ void __launch_bounds__(256) gather_kernel(
        const float* __restrict__ z,
        const float* __restrict__ inst,
        const float* __restrict__ mu,
        const float* __restrict__ sd,
        float*       __restrict__ out) {
    const int warp  = (blockIdx.x * blockDim.x + threadIdx.x) >> 5;
    const int lane  = threadIdx.x & 31;
    if (warp >= BB) return;
    const int bagid = warp;

    const unsigned long long p = g_seg[bagid];  // same addr across warp -> broadcast
    const bool  empty = (p == 0ULL);
    const int   idx   = empty ? 0 : (NN - (int)(unsigned)(p & 0xFFFFFFFFu));

    // Front-issue all loads (independent -> MLP=7 per lane).
    const float4* s_inst = reinterpret_cast<const float4*>(inst + (size_t)idx * FF);
    float4 iv0 = s_inst[lane +  0];
    float4 iv1 = s_inst[lane + 32];
    float4 iv2 = s_inst[lane + 64];
    float4 iv3 = s_inst[lane + 96];
    float4 zv  = reinterpret_cast<const float4*>(z  + (size_t)idx * DD)[lane];
    float4 mv  = reinterpret_cast<const float4*>(mu + (size_t)idx * DD)[lane];
    float4 sv  = reinterpret_cast<const float4*>(sd + (size_t)idx * DD)[lane];

    const float4 zero4 = make_float4(0.f, 0.f, 0.f, 0.f);
    if (empty) { iv0 = zero4; iv1 = zero4; iv2 = zero4; iv3 = zero4;
                 zv = zero4;  mv = zero4;  sv = zero4; }

    float4* o_inst = reinterpret_cast<float4*>(out + OFF_INST + (size_t)bagid * FF);
    o_inst[lane +  0] = iv0;
    o_inst[lane + 32] = iv1;
    o_inst[lane + 64] = iv2;
    o_inst[lane + 96] = iv3;
    reinterpret_cast<float4*>(out + OFF_Z   + (size_t)bagid * DD)[lane] = zv;
    reinterpret_cast<float4*>(out + OFF_MU  + (size_t)bagid * DD)[lane] = mv;
    reinterpret_cast<float4*>(out + OFF_STD + (size_t)bagid * DD)[lane] = sv;

    if (lane == 0) out[OFF_M + bagid] = empty ? 0.f : dec_float((unsigned)(p >> 32));

    // All lanes consumed p (read at warp entry); reset for next replay.
    __syncwarp();
    if (lane == 0) g_seg[bagid] = 0ULL;
}

extern "C" void kernel_launch(void* const* d_in, const int* in_sizes, int n_in,
                              void* d_out, int out_size) {
    const float* z_ins   = (const float*)d_in[0];
    const int*   bag_idx = (const int*)  d_in[1];
    const float* inst    = (const float*)d_in[2];
    const float* mu      = (const float*)d_in[3];
    const float* sd      = (const float*)d_in[4];
    const float* W       = (const float*)d_in[5];
    const float* b       = (const float*)d_in[6];
    float* out = (float*)d_out;

    const int blocks = (NN + ROWS_PER_BLOCK - 1) / ROWS_PER_BLOCK;
    loc_kernel<<<blocks, 256>>>(z_ins, bag_idx, W, b, out + OFF_LOC);

    // Warp per bag: 5000 warps -> 625 blocks of 256 threads.
    gather_kernel<<<(BB + 7) / 8, 256>>>(z_ins, inst, mu, sd, out);
}